// round 5
// baseline (speedup 1.0000x reference)
#include <cuda_runtime.h>

// Problem constants
#define NG   40      // groups
#define CPG  8       // channels per group (320/40)
#define ND   48      // disparity bins
#define NH   128
#define NW   240
#define NCC  12      // concat channels per tensor
#define PAD  48      // left zero-pad for shifted tgt (>= max d)
#define TROW (NW + PAD)   // 288 floats per padded tgt row
#define HW   (NH * NW)

// ---------------------------------------------------------------------------
// Kernel 1: groupwise-correlation volume. One block per (g, h), 192 threads.
// 180 active: 60 w-quads x 3 d-octet groups; k-loop of 2 covers all 48 d.
// Each thread owns a 4w x 8d register tile; ref (pre-scaled by 1/8) stays in
// registers across all 48 d; tgt window = 3 aligned LDS.128 per channel per
// 32 outputs.
// ---------------------------------------------------------------------------
__global__ __launch_bounds__(192) void gwc_kernel(const float* __restrict__ ref,
                                                  const float* __restrict__ tgt,
                                                  float* __restrict__ out) {
    __shared__ __align__(16) float sref[CPG * NW];    // 1920 floats
    __shared__ __align__(16) float stgt[CPG * TROW];  // 2304 floats

    const int g   = blockIdx.x;
    const int h   = blockIdx.y;
    const int tid = threadIdx.x;

    const float* gref = ref + ((size_t)(g * CPG) * NH + h) * NW;
    const float* gtgt = tgt + ((size_t)(g * CPG) * NH + h) * NW;

    for (int i = tid; i < CPG * (NW / 4); i += 192) {
        int c = i / (NW / 4), wq = i % (NW / 4);
        float4 v = *(const float4*)(gref + (size_t)c * HW + wq * 4);
        *(float4*)(sref + c * NW + wq * 4) = v;
    }
    for (int i = tid; i < CPG * (PAD / 4); i += 192) {
        int c = i / (PAD / 4), pq = i % (PAD / 4);
        *(float4*)(stgt + c * TROW + pq * 4) = make_float4(0.f, 0.f, 0.f, 0.f);
    }
    for (int i = tid; i < CPG * (NW / 4); i += 192) {
        int c = i / (NW / 4), wq = i % (NW / 4);
        float4 v = *(const float4*)(gtgt + (size_t)c * HW + wq * 4);
        *(float4*)(stgt + c * TROW + PAD + wq * 4) = v;
    }
    __syncthreads();

    const int wq   = tid & 63;    // 0..59 active per 64-thread slice
    const int dgrp = tid >> 6;    // 0..2
    if (wq >= NW / 4) return;
    const int w0 = wq * 4;

    // ref[c][w0..w0+3] * 0.125 held in registers across all 48 d
    float r[CPG][4];
#pragma unroll
    for (int c = 0; c < CPG; c++) {
        float4 v = *(const float4*)(sref + c * NW + w0);
        r[c][0] = v.x * 0.125f; r[c][1] = v.y * 0.125f;
        r[c][2] = v.z * 0.125f; r[c][3] = v.w * 0.125f;
    }

    float* outb = out + (size_t)g * ND * HW + (size_t)h * NW + w0;

#pragma unroll
    for (int k = 0; k < 2; k++) {
        const int d0 = (dgrp + 3 * k) * 8;     // d-octets 0..5 -> all 48 d
        float acc[8][4] = {};
#pragma unroll
        for (int c = 0; c < CPG; c++) {
            // window tgt[w0-d0-8 .. w0-d0+3], 16B-aligned
            const float* tp = stgt + c * TROW + PAD + w0 - d0 - 8;
            float4 v0 = *(const float4*)tp;
            float4 v1 = *(const float4*)(tp + 4);
            float4 v2 = *(const float4*)(tp + 8);
            float wv[12] = {v0.x, v0.y, v0.z, v0.w,
                            v1.x, v1.y, v1.z, v1.w,
                            v2.x, v2.y, v2.z, v2.w};
#pragma unroll
            for (int j = 0; j < 8; j++)
#pragma unroll
                for (int i = 0; i < 4; i++)
                    acc[j][i] += r[c][i] * wv[i + 8 - j];  // tgt[w0+i-(d0+j)]
        }
#pragma unroll
        for (int j = 0; j < 8; j++) {
            float4 o = make_float4(acc[j][0], acc[j][1], acc[j][2], acc[j][3]);
            *(float4*)(outb + (size_t)(d0 + j) * HW) = o;
        }
    }
}

// ---------------------------------------------------------------------------
// Kernel 2: concat volume. One block per (c_out, d); d uniform per block.
// Thread = (w-quad, h-lane); h-loop by pointer increment (no divides).
// Shift misalignment s = d&3 is compile-time specialized; masks precomputed.
// ---------------------------------------------------------------------------
template <int S>
__device__ __forceinline__ float4 shift_sel(float4 lo, float4 hi) {
    if (S == 0) return hi;
    if (S == 1) return make_float4(lo.w, hi.x, hi.y, hi.z);
    if (S == 2) return make_float4(lo.z, lo.w, hi.x, hi.y);
    return make_float4(lo.y, lo.z, lo.w, hi.x);
}

template <int S>
__device__ __forceinline__ void tgt_loop(const float* __restrict__ p, int o0, int o1,
                                         float* __restrict__ ob, int hy,
                                         bool k0, bool k1, bool k2, bool k3) {
#pragma unroll 4
    for (int h = hy; h < NH; h += 4) {
        float4 lo = (S != 0) ? *(const float4*)(p + (size_t)h * NW + o0)
                             : make_float4(0.f, 0.f, 0.f, 0.f);
        float4 hi = *(const float4*)(p + (size_t)h * NW + o1);
        float4 o = shift_sel<S>(lo, hi);
        o.x = k0 ? o.x : 0.f;
        o.y = k1 ? o.y : 0.f;
        o.z = k2 ? o.z : 0.f;
        o.w = k3 ? o.w : 0.f;
        *(float4*)(ob + (size_t)h * NW) = o;
    }
}

__global__ __launch_bounds__(256) void concat_kernel(const float* __restrict__ refc,
                                                     const float* __restrict__ tgtc,
                                                     float* __restrict__ out) {
    const int c   = blockIdx.x / ND;   // 0..23
    const int d   = blockIdx.x % ND;   // uniform per block
    const int tid = threadIdx.x;
    const int wq  = tid & 63;          // 0..59 active
    const int hy  = tid >> 6;          // 0..3
    if (wq >= NW / 4) return;
    const int w0 = wq * 4;

    const bool k0 = (w0 + 0 >= d), k1 = (w0 + 1 >= d),
               k2 = (w0 + 2 >= d), k3 = (w0 + 3 >= d);

    float* ob = out + ((size_t)(NG + c) * ND + d) * HW + w0;

    if (c < NCC) {
        // ref_concat masked by (w >= d)
        const float* p = refc + (size_t)c * HW + w0;
#pragma unroll 4
        for (int h = hy; h < NH; h += 4) {
            float4 v = *(const float4*)(p + (size_t)h * NW);
            v.x = k0 ? v.x : 0.f;
            v.y = k1 ? v.y : 0.f;
            v.z = k2 ? v.z : 0.f;
            v.w = k3 ? v.w : 0.f;
            *(float4*)(ob + (size_t)h * NW) = v;
        }
    } else {
        // tgt_concat shifted right by d (zero-fill left)
        const int s   = d & 3;
        const int dlo = d - s;
        const float* p = tgtc + (size_t)(c - NCC) * HW;
        const int a0 = w0 - dlo - 4;
        const int o0 = a0 < 0 ? 0 : a0;          // clamped aligned bases
        const int o1 = a0 + 4 < 0 ? 0 : a0 + 4;
        switch (s) {
            case 0:  tgt_loop<0>(p, o0, o1, ob, hy, k0, k1, k2, k3); break;
            case 1:  tgt_loop<1>(p, o0, o1, ob, hy, k0, k1, k2, k3); break;
            case 2:  tgt_loop<2>(p, o0, o1, ob, hy, k0, k1, k2, k3); break;
            default: tgt_loop<3>(p, o0, o1, ob, hy, k0, k1, k2, k3); break;
        }
    }
}

// ---------------------------------------------------------------------------
// Fork/join: run the two kernels concurrently as parallel graph branches.
// Streams/events are created lazily on the (uncaptured) correctness call and
// reused; every call performs the identical launch sequence.
// ---------------------------------------------------------------------------
extern "C" void kernel_launch(void* const* d_in, const int* in_sizes, int n_in,
                              void* d_out, int out_size) {
    (void)in_sizes; (void)n_in; (void)out_size;
    const float* ref_gwc = (const float*)d_in[0];
    const float* tgt_gwc = (const float*)d_in[1];
    const float* ref_c   = (const float*)d_in[2];
    const float* tgt_c   = (const float*)d_in[3];
    float* out = (float*)d_out;

    static cudaStream_t sA = nullptr, sB = nullptr;
    static cudaEvent_t  eF = nullptr, eA = nullptr, eB = nullptr;
    if (sA == nullptr) {
        cudaStreamCreateWithFlags(&sA, cudaStreamNonBlocking);
        cudaStreamCreateWithFlags(&sB, cudaStreamNonBlocking);
        cudaEventCreateWithFlags(&eF, cudaEventDisableTiming);
        cudaEventCreateWithFlags(&eA, cudaEventDisableTiming);
        cudaEventCreateWithFlags(&eB, cudaEventDisableTiming);
    }

    // fork from the capture (default) stream
    cudaEventRecord(eF, 0);
    cudaStreamWaitEvent(sA, eF, 0);
    cudaStreamWaitEvent(sB, eF, 0);

    gwc_kernel<<<dim3(NG, NH), 192, 0, sA>>>(ref_gwc, tgt_gwc, out);
    concat_kernel<<<2 * NCC * ND, 256, 0, sB>>>(ref_c, tgt_c, out);

    // join back into the capture stream
    cudaEventRecord(eA, sA);
    cudaEventRecord(eB, sB);
    cudaStreamWaitEvent(0, eA, 0);
    cudaStreamWaitEvent(0, eB, 0);
}